// round 5
// baseline (speedup 1.0000x reference)
#include <cuda_runtime.h>
#include <cstdint>

// ---------------------------------------------------------------------------
// Problem constants
// ---------------------------------------------------------------------------
#define MUL     16
#define DIM     64          // 4*MUL
#define SZ      5           // kernel size
#define NTAP    125
#define B_      2
#define NX      64
#define NY      64
#define NZ      64

// Effective conv weights: [tap][ci][co], tap = a*25 + b*5 + c
__device__ float g_W[NTAP * DIM * DIM];

// ---------------------------------------------------------------------------
// Kernel 1: build effective weights
//   Weff[t][ci][co] = 0.1 * K[t][ci][co]  (+ S[ci][co] at center tap t=62)
// ---------------------------------------------------------------------------
__global__ void build_weights(const float* __restrict__ lw0,
                              const float* __restrict__ lw1,
                              const float* __restrict__ tp)
{
    const int t  = blockIdx.x;            // 0..124
    const int a  = t / 25;
    const int b2 = (t / 5) % 5;
    const int c  = t % 5;

    const float lx = -1.f + 0.5f * (float)a;
    const float ly = -1.f + 0.5f * (float)b2;
    const float lz = -1.f + 0.5f * (float)c;
    const float d  = sqrtf(lx*lx + ly*ly + lz*lz);

    float ux = 0.f, uy = 0.f, uz = 0.f;
    if (d > 0.f) { ux = lx / d; uy = ly / d; uz = lz / d; }
    const float SQ3 = 1.7320508075688772f;
    const float sh1v0 = SQ3 * uy;   // sh1 = sqrt(3)*unit[[1,2,0]]
    const float sh1v1 = SQ3 * uz;
    const float sh1v2 = SQ3 * ux;

    // soft_one_hot * tp_weight, then * cos(pi d)/5^1.5
    const float scale = cosf(3.14159265358979323846f * d) / 11.180339887498949f;
    float coef[5];
#pragma unroll
    for (int s = 0; s < 5; s++) {
        float u = (d - 0.25f * (float)s) / 0.25f;
        coef[s] = expf(-u * u) * (1.0f / 1.12f) * scale;
    }

    float* W = g_W + t * (DIM * DIM);   // [ci][co]

    // zero the whole 64x64 tap slab first (non-covered entries are zero)
    for (int i = threadIdx.x; i < DIM * DIM; i += blockDim.x) W[i] = 0.f;
    __syncthreads();

    // one thread per (u,w) pair; 256 threads exactly
    const int u_ = threadIdx.x >> 4;   // 0..15
    const int w_ = threadIdx.x & 15;   // 0..15
    const int m  = u_ * 16 + w_;

    float eA = 0.f, eB = 0.f, eC = 0.f, eD = 0.f;
#pragma unroll
    for (int s = 0; s < 5; s++) {
        const float cs = coef[s];
        eA += cs * tp[s * 1024 +   0 + m];
        eB += cs * tp[s * 1024 + 256 + m];
        eC += cs * tp[s * 1024 + 512 + m];
        eD += cs * tp[s * 1024 + 768 + m];
    }

    const float A0  = 0.17677669529663689f;   // sqrt(1/32)
    const float A1  = 0.30618621784789724f;   // sqrt(3/32)
    const float IS3 = 0.57735026918962576f;   // 1/sqrt(3)
    const float inv = 0.25f;                  // 1/sqrt(MUL)
    const bool  center = (t == 62);           // (2,2,2)

    // k00: row u, col w
    {
        float v = 0.1f * A0 * eA;
        if (center) v += inv * lw0[u_ * 16 + w_];
        W[u_ * DIM + w_] = v;
    }
    // k01: row u, col 16 + 3w + k
    {
        const float base = 0.1f * A1 * IS3 * eB;
        W[u_ * DIM + 16 + w_ * 3 + 0] = base * sh1v0;
        W[u_ * DIM + 16 + w_ * 3 + 1] = base * sh1v1;
        W[u_ * DIM + 16 + w_ * 3 + 2] = base * sh1v2;
    }
    // k10: row 16 + 3u + i, col w      and k11 diagonal: col 16 + 3w + i
    {
        const float base10 = 0.1f * A0 * IS3 * eD;
        float v11 = 0.1f * A1 * IS3 * eC;
        if (center) v11 += inv * lw1[u_ * 16 + w_];
        const float sh[3] = { sh1v0, sh1v1, sh1v2 };
#pragma unroll
        for (int i = 0; i < 3; i++) {
            W[(16 + u_ * 3 + i) * DIM + w_]                = base10 * sh[i];
            W[(16 + u_ * 3 + i) * DIM + 16 + w_ * 3 + i]   = v11;
        }
    }
}

// ---------------------------------------------------------------------------
// f32x2 helpers (Blackwell packed dual-fp32 FMA; only reachable via PTX)
// ---------------------------------------------------------------------------
__device__ __forceinline__ unsigned long long dup_f32x2(float v) {
    unsigned long long r;
    asm("mov.b64 %0, {%1, %1};" : "=l"(r) : "f"(v));
    return r;
}
__device__ __forceinline__ void ffma2(unsigned long long& d,
                                      unsigned long long a,
                                      unsigned long long b) {
    asm("fma.rn.f32x2 %0, %1, %2, %0;" : "+l"(d) : "l"(a), "l"(b));
}
__device__ __forceinline__ void unpack2(unsigned long long v, float& lo, float& hi) {
    asm("mov.b64 {%0, %1}, %2;" : "=f"(lo), "=f"(hi) : "l"(v));
}

// ---------------------------------------------------------------------------
// Kernel 2: direct conv, block = (b, x0, y0), computes 64 cout x 64 z
//   smem: sIn[64 ci][72]  (z-halo, cols j -> z = j-2)
//         sW [5 c][64 ci][64 co]   (one (a,b) weight slab)
// ---------------------------------------------------------------------------
#define SIN_STRIDE 72
#define SIN_FLOATS (DIM * SIN_STRIDE)            // 4608
#define SW_FLOATS  (SZ * DIM * DIM)              // 20480
#define SMEM_BYTES ((SIN_FLOATS + SW_FLOATS) * 4)  // 100352

__global__ void __launch_bounds__(256, 2)
conv_kernel(const float* __restrict__ x, float* __restrict__ out)
{
    extern __shared__ float smem[];
    float* sIn = smem;                 // [64][72]
    float* sW  = smem + SIN_FLOATS;    // [5][64][64]

    const int gid = blockIdx.x;
    const int y0  = gid & 63;
    const int x0  = (gid >> 6) & 63;
    const int b   = gid >> 12;

    const int t  = threadIdx.x;
    const int zq = t & 15;     // z base = zq*4
    const int cq = t >> 4;     // co base = cq*4

    // acc[p][j]: f32x2 pair = (out[co=4cq+2p][z=4zq+j], out[co=4cq+2p+1][z])
    unsigned long long acc[2][4];
#pragma unroll
    for (int p = 0; p < 2; p++)
#pragma unroll
        for (int j = 0; j < 4; j++) acc[p][j] = 0ULL;

#pragma unroll 1
    for (int a = 0; a < 5; a++) {
        const int xi = x0 + a - 2;
        if ((unsigned)xi >= (unsigned)NX) continue;
#pragma unroll 1
        for (int bb = 0; bb < 5; bb++) {
            const int yi = y0 + bb - 2;
            if ((unsigned)yi >= (unsigned)NY) continue;

            __syncthreads();   // previous iteration's compute done before overwrite

            // load 64 input rows with z halo (cols 0..67; 68..71 unused pad)
            {
                const float* xb = x + ((((size_t)b * DIM) * NX + xi) * NY + yi) * NZ;
                for (int idx = t; idx < DIM * 68; idx += 256) {
                    const int ci = idx / 68;
                    const int j  = idx - ci * 68;
                    const int z  = j - 2;
                    float v = 0.f;
                    if ((unsigned)z < (unsigned)NZ)
                        v = xb[(size_t)ci * (NX * NY * NZ) + z];
                    sIn[ci * SIN_STRIDE + j] = v;
                }
            }
            // load weight slab for (a,bb): 5*64*64 floats, contiguous
            {
                const float4* src4 = (const float4*)(g_W + (size_t)(a * 5 + bb) * SW_FLOATS);
                float4* dst4 = (float4*)sW;
                for (int idx = t; idx < SW_FLOATS / 4; idx += 256)
                    dst4[idx] = src4[idx];
            }
            __syncthreads();

#pragma unroll 2
            for (int ci = 0; ci < DIM; ci++) {
                const float* row = &sIn[ci * SIN_STRIDE + (zq << 2)];
                const float4 f0 = *(const float4*)(row);
                const float4 f1 = *(const float4*)(row + 4);
                const float r[8] = { f0.x, f0.y, f0.z, f0.w,
                                     f1.x, f1.y, f1.z, f1.w };
                unsigned long long dup[8];
#pragma unroll
                for (int k = 0; k < 8; k++) dup[k] = dup_f32x2(r[k]);

#pragma unroll
                for (int c = 0; c < 5; c++) {
                    const ulonglong2 wp =
                        *(const ulonglong2*)&sW[((c * DIM) + ci) * DIM + (cq << 2)];
#pragma unroll
                    for (int j = 0; j < 4; j++) {
                        ffma2(acc[0][j], wp.x, dup[c + j]);
                        ffma2(acc[1][j], wp.y, dup[c + j]);
                    }
                }
            }
        }
    }

    // write: 4 cout x 4 z per thread, float4 along z
    const size_t obase = ((((size_t)b * DIM) * NX + x0) * NY + y0) * NZ + (zq << 2);
#pragma unroll
    for (int p = 0; p < 2; p++) {
        float lo0, hi0, lo1, hi1, lo2, hi2, lo3, hi3;
        unpack2(acc[p][0], lo0, hi0);
        unpack2(acc[p][1], lo1, hi1);
        unpack2(acc[p][2], lo2, hi2);
        unpack2(acc[p][3], lo3, hi3);
        const int co_lo = (cq << 2) + 2 * p;
        float4 vlo = { lo0, lo1, lo2, lo3 };
        float4 vhi = { hi0, hi1, hi2, hi3 };
        *(float4*)(out + obase + (size_t)co_lo       * (NX * NY * NZ)) = vlo;
        *(float4*)(out + obase + (size_t)(co_lo + 1) * (NX * NY * NZ)) = vhi;
    }
}

// ---------------------------------------------------------------------------
// Launch
// ---------------------------------------------------------------------------
extern "C" void kernel_launch(void* const* d_in, const int* in_sizes, int n_in,
                              void* d_out, int out_size)
{
    const float* x   = (const float*)d_in[0];   // (2,64,64,64,64)
    const float* lw0 = (const float*)d_in[1];   // (16,16)
    const float* lw1 = (const float*)d_in[2];   // (16,16)
    const float* tp  = (const float*)d_in[3];   // (5,1024)
    float* out = (float*)d_out;

    build_weights<<<NTAP, 256>>>(lw0, lw1, tp);

    cudaFuncSetAttribute(conv_kernel,
                         cudaFuncAttributeMaxDynamicSharedMemorySize, SMEM_BYTES);
    conv_kernel<<<B_ * NX * NY, 256, SMEM_BYTES>>>(x, out);
}

// round 7
// speedup vs baseline: 2.6790x; 2.6790x over previous
#include <cuda_runtime.h>
#include <cuda_bf16.h>
#include <cstdint>

#define DIM 64

// fp32 effective conv weights [tap][ci][co]
__device__ float g_W[125 * DIM * DIM];
// bf16 swizzled B slabs: [25 planes][hi 20480 | lo 20480] elems (k=320 rows x 64 n, xor-swizzled)
__device__ __align__(128) __nv_bfloat16 g_B[25 * 40960];
// channel-last bf16 split of x: [b][x][y][z][ci]
__device__ __align__(128) __nv_bfloat16 g_xhi[2ull * 64 * 64 * 64 * 64];
__device__ __align__(128) __nv_bfloat16 g_xlo[2ull * 64 * 64 * 64 * 64];
// 16B zero source for halo cp.async
__device__ __align__(16) float g_zero[4] = {0.f, 0.f, 0.f, 0.f};

// ---------------------------------------------------------------------------
// Kernel 1: effective fp32 weights (validated rounds 2-5)
// ---------------------------------------------------------------------------
__global__ void build_weights(const float* __restrict__ lw0,
                              const float* __restrict__ lw1,
                              const float* __restrict__ tp)
{
    const int t  = blockIdx.x;
    const int a  = t / 25;
    const int b2 = (t / 5) % 5;
    const int c  = t % 5;

    const float lx = -1.f + 0.5f * (float)a;
    const float ly = -1.f + 0.5f * (float)b2;
    const float lz = -1.f + 0.5f * (float)c;
    const float d  = sqrtf(lx*lx + ly*ly + lz*lz);

    float ux = 0.f, uy = 0.f, uz = 0.f;
    if (d > 0.f) { ux = lx / d; uy = ly / d; uz = lz / d; }
    const float SQ3 = 1.7320508075688772f;
    const float s0 = SQ3 * uy, s1 = SQ3 * uz, s2 = SQ3 * ux;

    const float scale = cosf(3.14159265358979323846f * d) / 11.180339887498949f;
    float coef[5];
#pragma unroll
    for (int s = 0; s < 5; s++) {
        float u = (d - 0.25f * (float)s) / 0.25f;
        coef[s] = expf(-u * u) * (1.0f / 1.12f) * scale;
    }

    float* W = g_W + t * (DIM * DIM);
    for (int i = threadIdx.x; i < DIM * DIM; i += blockDim.x) W[i] = 0.f;
    __syncthreads();

    const int u_ = threadIdx.x >> 4;
    const int w_ = threadIdx.x & 15;
    const int m  = u_ * 16 + w_;

    float eA = 0.f, eB = 0.f, eC = 0.f, eD = 0.f;
#pragma unroll
    for (int s = 0; s < 5; s++) {
        const float cs = coef[s];
        eA += cs * tp[s * 1024 +   0 + m];
        eB += cs * tp[s * 1024 + 256 + m];
        eC += cs * tp[s * 1024 + 512 + m];
        eD += cs * tp[s * 1024 + 768 + m];
    }

    const float A0  = 0.17677669529663689f;
    const float A1  = 0.30618621784789724f;
    const float IS3 = 0.57735026918962576f;
    const float inv = 0.25f;
    const bool  center = (t == 62);

    {
        float v = 0.1f * A0 * eA;
        if (center) v += inv * lw0[u_ * 16 + w_];
        W[u_ * DIM + w_] = v;
    }
    {
        const float base = 0.1f * A1 * IS3 * eB;
        W[u_ * DIM + 16 + w_ * 3 + 0] = base * s0;
        W[u_ * DIM + 16 + w_ * 3 + 1] = base * s1;
        W[u_ * DIM + 16 + w_ * 3 + 2] = base * s2;
    }
    {
        const float b10 = 0.1f * A0 * IS3 * eD;
        float v11 = 0.1f * A1 * IS3 * eC;
        if (center) v11 += inv * lw1[u_ * 16 + w_];
        const float sh[3] = { s0, s1, s2 };
#pragma unroll
        for (int i = 0; i < 3; i++) {
            W[(16 + u_ * 3 + i) * DIM + w_]              = b10 * sh[i];
            W[(16 + u_ * 3 + i) * DIM + 16 + w_ * 3 + i] = v11;
        }
    }
}

// ---------------------------------------------------------------------------
// Kernel 2: B slabs, bf16 hi/lo, rows k = c*64+ci (128B), XOR-swizzled cols
// ---------------------------------------------------------------------------
__global__ void build_B()
{
    const int t  = blockIdx.x;       // 0..124
    const int ss = t / 5;            // plane (a*5+bb)
    const int c  = t % 5;
    const float* W = g_W + t * 4096;

    __nv_bfloat16* hi = g_B + (size_t)ss * 40960;
    __nv_bfloat16* lo = hi + 20480;

    for (int idx = threadIdx.x; idx < 4096; idx += blockDim.x) {
        const int ci = idx >> 6;
        const int n  = idx & 63;
        const float v = W[ci * 64 + n];
        __nv_bfloat16 h = __float2bfloat16(v);
        __nv_bfloat16 l = __float2bfloat16(v - __bfloat162float(h));
        const int k = c * 64 + ci;
        const uint32_t off = (uint32_t)k * 128u
                           + (((uint32_t)n * 2u) ^ (((uint32_t)k & 7u) << 4));
        hi[off >> 1] = h;
        lo[off >> 1] = l;
    }
}

// ---------------------------------------------------------------------------
// Kernel 3: split + transpose x -> channel-last bf16 hi/lo
// ---------------------------------------------------------------------------
__global__ void __launch_bounds__(256) xsplit(const float* __restrict__ x)
{
    __shared__ float s[64][65];
    const int gid = blockIdx.x;            // b*4096 + xx*64 + y
    const int y  = gid & 63;
    const int xx = (gid >> 6) & 63;
    const int b  = gid >> 12;
    const int tid = threadIdx.x;
    const int zz = tid & 63;
    const int cq = tid >> 6;               // 0..3

    const size_t sp = (size_t)(xx * 64 + y) * 64;
#pragma unroll
    for (int r = 0; r < 16; r++) {
        const int ci = cq * 16 + r;
        s[ci][zz] = x[(size_t)(b * 64 + ci) * 262144 + sp + zz];
    }
    __syncthreads();

    __nv_bfloat16* oH = g_xhi + (((size_t)(b * 64 + xx) * 64 + y) << 12);
    __nv_bfloat16* oL = g_xlo + (((size_t)(b * 64 + xx) * 64 + y) << 12);
    const int ci_w = tid & 63;
#pragma unroll
    for (int r = 0; r < 16; r++) {
        const int z = cq * 16 + r;
        const float v = s[ci_w][z];
        __nv_bfloat16 h = __float2bfloat16(v);
        __nv_bfloat16 l = __float2bfloat16(v - __bfloat162float(h));
        oH[z * 64 + ci_w] = h;
        oL[z * 64 + ci_w] = l;
    }
}

// ---------------------------------------------------------------------------
// PTX helpers (all base-target sm_80+ instructions)
// ---------------------------------------------------------------------------
__device__ __forceinline__ uint32_t smem_u32(const void* p) {
    uint32_t a;
    asm("{ .reg .u64 t; cvta.to.shared.u64 t, %1; cvt.u32.u64 %0, t; }"
        : "=r"(a) : "l"(p));
    return a;
}
__device__ __forceinline__ void ldsm4(uint32_t& r0, uint32_t& r1,
                                      uint32_t& r2, uint32_t& r3, uint32_t a) {
    asm volatile("ldmatrix.sync.aligned.m8n8.x4.shared.b16 {%0,%1,%2,%3}, [%4];"
                 : "=r"(r0), "=r"(r1), "=r"(r2), "=r"(r3) : "r"(a));
}
__device__ __forceinline__ void ldsm4t(uint32_t& r0, uint32_t& r1,
                                       uint32_t& r2, uint32_t& r3, uint32_t a) {
    asm volatile("ldmatrix.sync.aligned.m8n8.x4.trans.shared.b16 {%0,%1,%2,%3}, [%4];"
                 : "=r"(r0), "=r"(r1), "=r"(r2), "=r"(r3) : "r"(a));
}
__device__ __forceinline__ void mma16816(float* d, uint32_t a0, uint32_t a1,
                                         uint32_t a2, uint32_t a3,
                                         uint32_t b0, uint32_t b1) {
    asm volatile(
        "mma.sync.aligned.m16n8k16.row.col.f32.bf16.bf16.f32 "
        "{%0,%1,%2,%3}, {%4,%5,%6,%7}, {%8,%9}, {%0,%1,%2,%3};"
        : "+f"(d[0]), "+f"(d[1]), "+f"(d[2]), "+f"(d[3])
        : "r"(a0), "r"(a1), "r"(a2), "r"(a3), "r"(b0), "r"(b1));
}
__device__ __forceinline__ void cpa16(uint32_t dst, const void* src) {
    asm volatile("cp.async.cg.shared.global [%0], [%1], 16;"
                 :: "r"(dst), "l"(src));
}
#define CP_COMMIT() asm volatile("cp.async.commit_group;" ::: "memory")
#define CP_WAIT0()  asm volatile("cp.async.wait_group 0;" ::: "memory")

// ---------------------------------------------------------------------------
// SMEM map (bytes, within dynamic smem)
//   B slabs : 2 bufs x [hi 40960 | lo 40960]      = 163840
//   Input   : 4 x (ys,half) x 68 rows x 128B      =  34816
// ---------------------------------------------------------------------------
#define SM_B    0
#define SM_IN   163840
#define SM_TOT  198656

// ---------------------------------------------------------------------------
// Kernel 4: mma.sync implicit-GEMM conv
//   CTA = (b, x0, y0 pair). M=128 (2y x 64z), N=64, 25 (a,bb) planes.
// ---------------------------------------------------------------------------
__global__ void __launch_bounds__(256, 1)
conv_mma(float* __restrict__ out)
{
    extern __shared__ char smem[];
    const uint32_t sb = smem_u32(smem);
    const int tid  = threadIdx.x;
    const int wid  = tid >> 5;
    const int lane = tid & 31;

    const int gid = blockIdx.x;
    const int y0  = (gid & 31) * 2;
    const int x0  = (gid >> 5) & 63;
    const int b   = gid >> 11;

    // zero halo rows j = 0,1,66,67 of all 4 input sub-buffers (never rewritten)
    if (tid < 128) {
        const int buf  = tid >> 5;            // (ys*2 + half)
        const int rsel = (tid >> 3) & 3;
        const int col  = tid & 7;
        const int j    = (rsel < 2) ? rsel : (rsel + 64);
        const uint32_t dst = sb + SM_IN + buf * 8704 + j * 128
                           + (((uint32_t)col * 16u) ^ (((uint32_t)j & 7u) << 4));
        *(float4*)(smem + (dst - sb)) = make_float4(0.f, 0.f, 0.f, 0.f);
    }

    // plane list (uniform across block)
    int pslab[25], pxi[25], pbb[25];
    int npl = 0;
#pragma unroll
    for (int a = 0; a < 5; a++) {
        const int xi = x0 + a - 2;
        if ((unsigned)xi >= 64u) continue;
#pragma unroll
        for (int bb = 0; bb < 5; bb++) {
            const int yi0 = y0 + bb - 2;
            const int yi1 = yi0 + 1;
            if ((unsigned)yi0 >= 64u && (unsigned)yi1 >= 64u) continue;
            pslab[npl] = a * 5 + bb;
            pxi[npl]   = xi;
            pbb[npl]   = bb;
            npl++;
        }
    }

    // per-warp / per-thread constants
    const int zb   = (wid & 3) * 16;                 // z base of this warp's m16
    const int ysw  = wid >> 2;                       // ys of this warp
    const int mloc = (lane & 7) + ((lane >> 3) & 1) * 8;
    const int ksub = lane >> 4;                      // 0/1 -> +16B column
    const uint32_t inWbase = sb + SM_IN + ysw * 17408;   // ysw's hi buffer
    float acc[8][4];
#pragma unroll
    for (int nt = 0; nt < 8; nt++)
#pragma unroll
        for (int i = 0; i < 4; i++) acc[nt][i] = 0.f;

    // staging lambdas -------------------------------------------------------
    auto stage_B = [&](int p, int buf) {
        const __nv_bfloat16* src = g_B + (size_t)pslab[p] * 40960;
        const uint32_t dst0 = sb + SM_B + buf * 81920;
#pragma unroll
        for (int i = 0; i < 20; i++) {
            const int id = tid + i * 256;            // 0..5119
            cpa16(dst0 + id * 16, src + id * 8);
        }
    };
    auto stage_In = [&](int p) {
        const int xi = pxi[p], bb = pbb[p];
#pragma unroll
        for (int i = 0; i < 8; i++) {
            const int id   = tid + i * 256;          // 0..2047
            const int col  = id & 7;
            const int z    = (id >> 3) & 63;
            const int half = (id >> 9) & 1;
            const int ys   = id >> 10;
            const int yi   = y0 + ys + bb - 2;
            const bool ok  = (unsigned)yi < 64u;
            const __nv_bfloat16* g = half ? g_xlo : g_xhi;
            const void* src = ok
                ? (const void*)(g + (((size_t)(b * 64 + xi) * 64 + yi) << 12)
                                + z * 64 + col * 8)
                : (const void*)g_zero;
            const int j = z + 2;
            const uint32_t dst = sb + SM_IN + (ys * 2 + half) * 8704 + j * 128
                               + (((uint32_t)col * 16u) ^ (((uint32_t)j & 7u) << 4));
            cpa16(dst, src);
        }
    };

    // prologue
    stage_B(0, 0);
    stage_In(0);
    CP_COMMIT();
    CP_WAIT0();
    __syncthreads();

#pragma unroll 1
    for (int p = 0; p < npl; p++) {
        if (p + 1 < npl) { stage_B(p + 1, (p + 1) & 1); CP_COMMIT(); }

        const uint32_t bbH = sb + SM_B + (p & 1) * 81920;
        const uint32_t bbL = bbH + 40960;

        // ---- compute: 5 c-taps x 4 ci-blocks of k16 ----
#pragma unroll 1
        for (int c = 0; c < 5; c++) {
            const int jj = zb + mloc + c;            // input row (z+c)
            const uint32_t jx = ((uint32_t)jj & 7u) << 4;
            const uint32_t arow = (uint32_t)jj * 128u;
#pragma unroll
            for (int q = 0; q < 4; q++) {            // ci0 = q*16
                const uint32_t acol = ((uint32_t)(q * 32 + ksub * 16)) ^ jx;
                uint32_t ah0, ah1, ah2, ah3, al0, al1, al2, al3;
                ldsm4(ah0, ah1, ah2, ah3, inWbase + arow + acol);
                ldsm4(al0, al1, al2, al3, inWbase + 8704 + arow + acol);

                const int krow = c * 64 + q * 16 + mloc;
                const uint32_t kx = ((uint32_t)krow & 7u) << 4;
                const uint32_t brow = (uint32_t)krow * 128u;
#pragma unroll
                for (int nq = 0; nq < 4; nq++) {     // n0 = nq*16 -> ntiles 2nq,2nq+1
                    const uint32_t bcol = ((uint32_t)(nq * 32 + ksub * 16)) ^ kx;
                    uint32_t bh0, bh1, bh2, bh3, bl0, bl1, bl2, bl3;
                    ldsm4t(bh0, bh1, bh2, bh3, bbH + brow + bcol);
                    ldsm4t(bl0, bl1, bl2, bl3, bbL + brow + bcol);
                    float* d0 = acc[2 * nq];
                    float* d1 = acc[2 * nq + 1];
                    mma16816(d0, ah0, ah1, ah2, ah3, bh0, bh1);
                    mma16816(d1, ah0, ah1, ah2, ah3, bh2, bh3);
                    mma16816(d0, al0, al1, al2, al3, bh0, bh1);
                    mma16816(d1, al0, al1, al2, al3, bh2, bh3);
                    mma16816(d0, ah0, ah1, ah2, ah3, bl0, bl1);
                    mma16816(d1, ah0, ah1, ah2, ah3, bl2, bl3);
                }
            }
        }
        __syncthreads();                 // done reading input + B(p)
        if (p + 1 < npl) {
            stage_In(p + 1);
            CP_COMMIT();
            CP_WAIT0();                  // waits In(p+1) and B(p+1)
        }
        __syncthreads();
    }

    // ---- epilogue: direct global stores ----
    // D[m][n]: m = wid*16 + g (+8), n = nt*8 + 2c' (+1); z = zb + g, y = y0+ysw
    const int g  = lane >> 2;
    const int cc = lane & 3;
    const int z  = zb + g;
    const int y  = y0 + ysw;
    float* ob = out + ((((size_t)b * 64) * 64 + x0) * 64 + y) * 64 + z;
#pragma unroll
    for (int nt = 0; nt < 8; nt++) {
        const int n = nt * 8 + 2 * cc;
        float* p0 = ob + (size_t)n * 262144;
        float* p1 = ob + (size_t)(n + 1) * 262144;
        p0[0] = acc[nt][0];
        p1[0] = acc[nt][1];
        p0[8] = acc[nt][2];
        p1[8] = acc[nt][3];
    }
}

// ---------------------------------------------------------------------------
// Launch
// ---------------------------------------------------------------------------
extern "C" void kernel_launch(void* const* d_in, const int* in_sizes, int n_in,
                              void* d_out, int out_size)
{
    const float* x   = (const float*)d_in[0];
    const float* lw0 = (const float*)d_in[1];
    const float* lw1 = (const float*)d_in[2];
    const float* tp  = (const float*)d_in[3];
    float* out = (float*)d_out;

    xsplit<<<2 * 64 * 64, 256>>>(x);
    build_weights<<<125, 256>>>(lw0, lw1, tp);
    build_B<<<125, 256>>>();

    cudaFuncSetAttribute(conv_mma, cudaFuncAttributeMaxDynamicSharedMemorySize,
                         SM_TOT);
    conv_mma<<<2 * 64 * 32, 256, SM_TOT>>>(out);
}

// round 8
// speedup vs baseline: 2.8151x; 1.0508x over previous
#include <cuda_runtime.h>
#include <cuda_bf16.h>
#include <cstdint>

#define DIM 64

// fp32 effective conv weights [tap][ci][co]
__device__ float g_W[125 * DIM * DIM];
// bf16 swizzled B slabs: [25 planes][hi 20480 | lo 20480] elems (k=320 rows x 64 n)
__device__ __align__(128) __nv_bfloat16 g_B[25 * 40960];
// channel-last bf16 split of x: [b][x][y][z][ci]
__device__ __align__(128) __nv_bfloat16 g_xhi[2ull * 64 * 64 * 64 * 64];
__device__ __align__(128) __nv_bfloat16 g_xlo[2ull * 64 * 64 * 64 * 64];
// 16B zero source for halo cp.async
__device__ __align__(16) float g_zero[4] = {0.f, 0.f, 0.f, 0.f};

// ---------------------------------------------------------------------------
// Kernel 1: effective fp32 weights (validated rounds 2-7)
// ---------------------------------------------------------------------------
__global__ void build_weights(const float* __restrict__ lw0,
                              const float* __restrict__ lw1,
                              const float* __restrict__ tp)
{
    const int t  = blockIdx.x;
    const int a  = t / 25;
    const int b2 = (t / 5) % 5;
    const int c  = t % 5;

    const float lx = -1.f + 0.5f * (float)a;
    const float ly = -1.f + 0.5f * (float)b2;
    const float lz = -1.f + 0.5f * (float)c;
    const float d  = sqrtf(lx*lx + ly*ly + lz*lz);

    float ux = 0.f, uy = 0.f, uz = 0.f;
    if (d > 0.f) { ux = lx / d; uy = ly / d; uz = lz / d; }
    const float SQ3 = 1.7320508075688772f;
    const float s0 = SQ3 * uy, s1 = SQ3 * uz, s2 = SQ3 * ux;

    const float scale = cosf(3.14159265358979323846f * d) / 11.180339887498949f;
    float coef[5];
#pragma unroll
    for (int s = 0; s < 5; s++) {
        float u = (d - 0.25f * (float)s) / 0.25f;
        coef[s] = expf(-u * u) * (1.0f / 1.12f) * scale;
    }

    float* W = g_W + t * (DIM * DIM);
    for (int i = threadIdx.x; i < DIM * DIM; i += blockDim.x) W[i] = 0.f;
    __syncthreads();

    const int u_ = threadIdx.x >> 4;
    const int w_ = threadIdx.x & 15;
    const int m  = u_ * 16 + w_;

    float eA = 0.f, eB = 0.f, eC = 0.f, eD = 0.f;
#pragma unroll
    for (int s = 0; s < 5; s++) {
        const float cs = coef[s];
        eA += cs * tp[s * 1024 +   0 + m];
        eB += cs * tp[s * 1024 + 256 + m];
        eC += cs * tp[s * 1024 + 512 + m];
        eD += cs * tp[s * 1024 + 768 + m];
    }

    const float A0  = 0.17677669529663689f;
    const float A1  = 0.30618621784789724f;
    const float IS3 = 0.57735026918962576f;
    const float inv = 0.25f;
    const bool  center = (t == 62);

    {
        float v = 0.1f * A0 * eA;
        if (center) v += inv * lw0[u_ * 16 + w_];
        W[u_ * DIM + w_] = v;
    }
    {
        const float base = 0.1f * A1 * IS3 * eB;
        W[u_ * DIM + 16 + w_ * 3 + 0] = base * s0;
        W[u_ * DIM + 16 + w_ * 3 + 1] = base * s1;
        W[u_ * DIM + 16 + w_ * 3 + 2] = base * s2;
    }
    {
        const float b10 = 0.1f * A0 * IS3 * eD;
        float v11 = 0.1f * A1 * IS3 * eC;
        if (center) v11 += inv * lw1[u_ * 16 + w_];
        const float sh[3] = { s0, s1, s2 };
#pragma unroll
        for (int i = 0; i < 3; i++) {
            W[(16 + u_ * 3 + i) * DIM + w_]              = b10 * sh[i];
            W[(16 + u_ * 3 + i) * DIM + 16 + w_ * 3 + i] = v11;
        }
    }
}

// ---------------------------------------------------------------------------
// Kernel 2: B slabs, bf16 hi/lo, rows k = c*64+ci (128B), XOR-swizzled cols
// ---------------------------------------------------------------------------
__global__ void build_B()
{
    const int t  = blockIdx.x;       // 0..124
    const int ss = t / 5;            // plane (a*5+bb)
    const int c  = t % 5;
    const float* W = g_W + t * 4096;

    __nv_bfloat16* hi = g_B + (size_t)ss * 40960;
    __nv_bfloat16* lo = hi + 20480;

    for (int idx = threadIdx.x; idx < 4096; idx += blockDim.x) {
        const int ci = idx >> 6;
        const int n  = idx & 63;
        const float v = W[ci * 64 + n];
        __nv_bfloat16 h = __float2bfloat16(v);
        __nv_bfloat16 l = __float2bfloat16(v - __bfloat162float(h));
        const int k = c * 64 + ci;
        const uint32_t off = (uint32_t)k * 128u
                           + (((uint32_t)n * 2u) ^ (((uint32_t)k & 7u) << 4));
        hi[off >> 1] = h;
        lo[off >> 1] = l;
    }
}

// ---------------------------------------------------------------------------
// Kernel 3: split + transpose x -> channel-last bf16 hi/lo
// ---------------------------------------------------------------------------
__global__ void __launch_bounds__(256) xsplit(const float* __restrict__ x)
{
    __shared__ float s[64][65];
    const int gid = blockIdx.x;            // b*4096 + xx*64 + y
    const int y  = gid & 63;
    const int xx = (gid >> 6) & 63;
    const int b  = gid >> 12;
    const int tid = threadIdx.x;
    const int zz = tid & 63;
    const int cq = tid >> 6;               // 0..3

    const size_t sp = (size_t)(xx * 64 + y) * 64;
#pragma unroll
    for (int r = 0; r < 16; r++) {
        const int ci = cq * 16 + r;
        s[ci][zz] = x[(size_t)(b * 64 + ci) * 262144 + sp + zz];
    }
    __syncthreads();

    __nv_bfloat16* oH = g_xhi + (((size_t)(b * 64 + xx) * 64 + y) << 12);
    __nv_bfloat16* oL = g_xlo + (((size_t)(b * 64 + xx) * 64 + y) << 12);
    const int ci_w = tid & 63;
#pragma unroll
    for (int r = 0; r < 16; r++) {
        const int z = cq * 16 + r;
        const float v = s[ci_w][z];
        __nv_bfloat16 h = __float2bfloat16(v);
        __nv_bfloat16 l = __float2bfloat16(v - __bfloat162float(h));
        oH[z * 64 + ci_w] = h;
        oL[z * 64 + ci_w] = l;
    }
}

// ---------------------------------------------------------------------------
// PTX helpers (all base-target sm_80+ instructions)
// ---------------------------------------------------------------------------
__device__ __forceinline__ uint32_t smem_u32(const void* p) {
    uint32_t a;
    asm("{ .reg .u64 t; cvta.to.shared.u64 t, %1; cvt.u32.u64 %0, t; }"
        : "=r"(a) : "l"(p));
    return a;
}
__device__ __forceinline__ void ldsm4(uint32_t& r0, uint32_t& r1,
                                      uint32_t& r2, uint32_t& r3, uint32_t a) {
    asm volatile("ldmatrix.sync.aligned.m8n8.x4.shared.b16 {%0,%1,%2,%3}, [%4];"
                 : "=r"(r0), "=r"(r1), "=r"(r2), "=r"(r3) : "r"(a));
}
__device__ __forceinline__ void ldsm4t(uint32_t& r0, uint32_t& r1,
                                       uint32_t& r2, uint32_t& r3, uint32_t a) {
    asm volatile("ldmatrix.sync.aligned.m8n8.x4.trans.shared.b16 {%0,%1,%2,%3}, [%4];"
                 : "=r"(r0), "=r"(r1), "=r"(r2), "=r"(r3) : "r"(a));
}
__device__ __forceinline__ void mma16816(float* d, uint32_t a0, uint32_t a1,
                                         uint32_t a2, uint32_t a3,
                                         uint32_t b0, uint32_t b1) {
    asm volatile(
        "mma.sync.aligned.m16n8k16.row.col.f32.bf16.bf16.f32 "
        "{%0,%1,%2,%3}, {%4,%5,%6,%7}, {%8,%9}, {%0,%1,%2,%3};"
        : "+f"(d[0]), "+f"(d[1]), "+f"(d[2]), "+f"(d[3])
        : "r"(a0), "r"(a1), "r"(a2), "r"(a3), "r"(b0), "r"(b1));
}
__device__ __forceinline__ void cpa16(uint32_t dst, const void* src) {
    asm volatile("cp.async.cg.shared.global [%0], [%1], 16;"
                 :: "r"(dst), "l"(src));
}
#define CP_COMMIT() asm volatile("cp.async.commit_group;" ::: "memory")
#define CP_WAIT0()  asm volatile("cp.async.wait_group 0;" ::: "memory")

// ---------------------------------------------------------------------------
// SMEM map (bytes, within dynamic smem)
//   B slabs : 2 bufs x [hi 40960 | lo 40960]            = 163840
//   Input   : 2 stages x 4 (ys,half) x 64 rows x 128B   =  65536
//   Zero row: 128B shared halo row                       (+pad)
// ---------------------------------------------------------------------------
#define SM_B    0
#define SM_IN   163840
#define SM_ZERO 229376
#define SM_TOT  229504

// ---------------------------------------------------------------------------
// Kernel 4: mma.sync implicit-GEMM conv, fully double-buffered pipeline
//   CTA = (b, x0, y0 pair). M=128 (2y x 64z), N=64, 25 (a,bb) planes.
// ---------------------------------------------------------------------------
__global__ void __launch_bounds__(256, 1)
conv_mma(float* __restrict__ out)
{
    extern __shared__ char smem[];
    const uint32_t sb = smem_u32(smem);
    const int tid  = threadIdx.x;
    const int wid  = tid >> 5;
    const int lane = tid & 31;

    const int gid = blockIdx.x;
    const int y0  = (gid & 31) * 2;
    const int x0  = (gid >> 5) & 63;
    const int b   = gid >> 11;

    // init shared zero halo row (used by out-of-range ldmatrix lanes)
    if (tid < 8)
        *(float4*)(smem + SM_ZERO + tid * 16) = make_float4(0.f, 0.f, 0.f, 0.f);

    // plane list (uniform across block)
    int pslab[25], pxi[25], pbb[25];
    int npl = 0;
#pragma unroll
    for (int a = 0; a < 5; a++) {
        const int xi = x0 + a - 2;
        if ((unsigned)xi >= 64u) continue;
#pragma unroll
        for (int bb = 0; bb < 5; bb++) {
            const int yi0 = y0 + bb - 2;
            const int yi1 = yi0 + 1;
            if ((unsigned)yi0 >= 64u && (unsigned)yi1 >= 64u) continue;
            pslab[npl] = a * 5 + bb;
            pxi[npl]   = xi;
            pbb[npl]   = bb;
            npl++;
        }
    }

    // per-warp / per-thread constants
    const int zb   = (wid & 3) * 16;                 // z base of this warp's m16
    const int ysw  = wid >> 2;                       // ys of this warp
    const int mloc = (lane & 7) + ((lane >> 3) & 1) * 8;
    const int ksub = lane >> 4;                      // 0/1 -> +16B column
    const uint32_t zeroAddr = sb + SM_ZERO;
    float acc[8][4];
#pragma unroll
    for (int nt = 0; nt < 8; nt++)
#pragma unroll
        for (int i = 0; i < 4; i++) acc[nt][i] = 0.f;

    // staging lambdas -------------------------------------------------------
    auto stage_B = [&](int p, int buf) {
        const __nv_bfloat16* src = g_B + (size_t)pslab[p] * 40960;
        const uint32_t dst0 = sb + SM_B + buf * 81920;
#pragma unroll
        for (int i = 0; i < 20; i++) {
            const int id = tid + i * 256;            // 0..5119
            cpa16(dst0 + id * 16, src + id * 8);
        }
    };
    auto stage_In = [&](int p, int stg) {
        const int xi = pxi[p], bb = pbb[p];
#pragma unroll
        for (int i = 0; i < 8; i++) {
            const int id   = tid + i * 256;          // 0..2047
            const int col  = id & 7;
            const int z    = (id >> 3) & 63;
            const int half = (id >> 9) & 1;
            const int ys   = id >> 10;
            const int yi   = y0 + ys + bb - 2;
            const bool ok  = (unsigned)yi < 64u;
            const __nv_bfloat16* g = half ? g_xlo : g_xhi;
            const void* src = ok
                ? (const void*)(g + (((size_t)(b * 64 + xi) * 64 + yi) << 12)
                                + z * 64 + col * 8)
                : (const void*)g_zero;
            const uint32_t dst = sb + SM_IN + stg * 32768
                               + (ys * 2 + half) * 8192 + z * 128
                               + (((uint32_t)col * 16u) ^ (((uint32_t)z & 7u) << 4));
            cpa16(dst, src);
        }
    };

    // prologue
    stage_B(0, 0);
    stage_In(0, 0);
    CP_COMMIT();
    CP_WAIT0();
    __syncthreads();

#pragma unroll 1
    for (int p = 0; p < npl; p++) {
        // prefetch next plane into the other buffers (fully overlapped)
        if (p + 1 < npl) {
            stage_B(p + 1, (p + 1) & 1);
            stage_In(p + 1, (p + 1) & 1);
            CP_COMMIT();
        }

        const uint32_t bbH = sb + SM_B + (p & 1) * 81920;
        const uint32_t bbL = bbH + 40960;
        const uint32_t inH = sb + SM_IN + (p & 1) * 32768 + ysw * 16384;
        const uint32_t inL = inH + 8192;

        // ---- compute: 5 c-taps x 4 ci-blocks of k16 ----
#pragma unroll 1
        for (int c = 0; c < 5; c++) {
            const int zi = zb + mloc + c - 2;        // input z row (per lane)
            const bool vz = (unsigned)zi < 64u;
            const uint32_t jx   = ((uint32_t)zi & 7u) << 4;
            const uint32_t arow = (uint32_t)zi * 128u;
#pragma unroll
            for (int q = 0; q < 4; q++) {            // ci0 = q*16
                const uint32_t acol = ((uint32_t)(q * 32 + ksub * 16)) ^ jx;
                const uint32_t aH = vz ? (inH + arow + acol) : zeroAddr;
                const uint32_t aL = vz ? (inL + arow + acol) : zeroAddr;
                uint32_t ah0, ah1, ah2, ah3, al0, al1, al2, al3;
                ldsm4(ah0, ah1, ah2, ah3, aH);
                ldsm4(al0, al1, al2, al3, aL);

                const int krow = c * 64 + q * 16 + mloc;
                const uint32_t kx = ((uint32_t)krow & 7u) << 4;
                const uint32_t brow = (uint32_t)krow * 128u;
#pragma unroll
                for (int nq = 0; nq < 4; nq++) {     // n0 = nq*16 -> ntiles 2nq,2nq+1
                    const uint32_t bcol = ((uint32_t)(nq * 32 + ksub * 16)) ^ kx;
                    uint32_t bh0, bh1, bh2, bh3, bl0, bl1, bl2, bl3;
                    ldsm4t(bh0, bh1, bh2, bh3, bbH + brow + bcol);
                    ldsm4t(bl0, bl1, bl2, bl3, bbL + brow + bcol);
                    float* d0 = acc[2 * nq];
                    float* d1 = acc[2 * nq + 1];
                    mma16816(d0, ah0, ah1, ah2, ah3, bh0, bh1);
                    mma16816(d1, ah0, ah1, ah2, ah3, bh2, bh3);
                    mma16816(d0, al0, al1, al2, al3, bh0, bh1);
                    mma16816(d1, al0, al1, al2, al3, bh2, bh3);
                    mma16816(d0, ah0, ah1, ah2, ah3, bl0, bl1);
                    mma16816(d1, ah0, ah1, ah2, ah3, bl2, bl3);
                }
            }
        }

        if (p + 1 < npl) CP_WAIT0();   // copies have had the whole compute to land
        __syncthreads();               // all warps done reading bufs p; bufs p+1 ready
    }

    // ---- epilogue: direct global stores ----
    const int g  = lane >> 2;
    const int cc = lane & 3;
    const int z  = zb + g;
    const int y  = y0 + ysw;
    float* ob = out + ((((size_t)b * 64) * 64 + x0) * 64 + y) * 64 + z;
#pragma unroll
    for (int nt = 0; nt < 8; nt++) {
        const int n = nt * 8 + 2 * cc;
        float* p0 = ob + (size_t)n * 262144;
        float* p1 = ob + (size_t)(n + 1) * 262144;
        p0[0] = acc[nt][0];
        p1[0] = acc[nt][1];
        p0[8] = acc[nt][2];
        p1[8] = acc[nt][3];
    }
}

// ---------------------------------------------------------------------------
// Launch
// ---------------------------------------------------------------------------
extern "C" void kernel_launch(void* const* d_in, const int* in_sizes, int n_in,
                              void* d_out, int out_size)
{
    const float* x   = (const float*)d_in[0];
    const float* lw0 = (const float*)d_in[1];
    const float* lw1 = (const float*)d_in[2];
    const float* tp  = (const float*)d_in[3];
    float* out = (float*)d_out;

    xsplit<<<2 * 64 * 64, 256>>>(x);
    build_weights<<<125, 256>>>(lw0, lw1, tp);
    build_B<<<125, 256>>>();

    cudaFuncSetAttribute(conv_mma, cudaFuncAttributeMaxDynamicSharedMemorySize,
                         SM_TOT);
    conv_mma<<<2 * 64 * 32, 256, SM_TOT>>>(out);
}